// round 1
// baseline (speedup 1.0000x reference)
#include <cuda_runtime.h>
#include <cstdint>

// ---------------------------------------------------------------------------
// Problem constants
//   q    [4, 2048, 1024]  (pre-projected queries, head h at cols h*64..h*64+63)
//   c    [4, 2048, 1024]
//   W_kv [1024, 2048], b_kv [2048]
//   W_o  [1024, 1024], b_o  [1024]
//   out  [4, 2048, 1024] fp32
// kv scratch layout: [b][s][2048]; head h: K at cols h*128..+63, V at h*128+64..+127
// ---------------------------------------------------------------------------

#define BATCH 4
#define SEQ   2048
#define EMB   1024
#define NH    16
#define HD    64

__device__ float g_kv[(size_t)BATCH * SEQ * 2 * EMB];    // 64 MB
__device__ float g_vals[(size_t)BATCH * SEQ * EMB];      // 32 MB

// ======================= SGEMM with bias (C = A*B + bias) ==================
// A [M,K] row-major, B [K,N] row-major, bias [N]. M%128==0, N%128==0, K%16==0.
#define GBM 128
#define GBN 128
#define GBK 16
__global__ __launch_bounds__(256, 2)
void sgemm_bias_kernel(const float* __restrict__ A, const float* __restrict__ B,
                       const float* __restrict__ bias, float* __restrict__ C,
                       int M, int N, int K)
{
    __shared__ float As[GBK][GBM];   // transposed A tile
    __shared__ float Bs[GBK][GBN];

    const int tid  = threadIdx.x;
    const int brow = blockIdx.y * GBM;
    const int bcol = blockIdx.x * GBN;

    const int a_row = tid >> 2;          // 0..63
    const int a_c4  = (tid & 3) * 4;     // 0,4,8,12
    const int b_row = tid >> 5;          // 0..7
    const int b_c4  = (tid & 31) * 4;    // 0..124

    const int ty = tid >> 4, tx = tid & 15;

    float acc[8][8];
    #pragma unroll
    for (int i = 0; i < 8; i++)
        #pragma unroll
        for (int j = 0; j < 8; j++) acc[i][j] = 0.f;

    for (int k0 = 0; k0 < K; k0 += GBK) {
        // load A tile (128x16), store transposed
        #pragma unroll
        for (int i = 0; i < 2; i++) {
            int r = a_row + i * 64;
            float4 v = *(const float4*)&A[(size_t)(brow + r) * K + k0 + a_c4];
            As[a_c4 + 0][r] = v.x;
            As[a_c4 + 1][r] = v.y;
            As[a_c4 + 2][r] = v.z;
            As[a_c4 + 3][r] = v.w;
        }
        // load B tile (16x128)
        #pragma unroll
        for (int i = 0; i < 2; i++) {
            int r = b_row + i * 8;
            *(float4*)&Bs[r][b_c4] =
                *(const float4*)&B[(size_t)(k0 + r) * N + bcol + b_c4];
        }
        __syncthreads();

        #pragma unroll
        for (int kk = 0; kk < GBK; kk++) {
            float4 a0 = *(const float4*)&As[kk][ty * 8];
            float4 a1 = *(const float4*)&As[kk][ty * 8 + 4];
            float4 b0 = *(const float4*)&Bs[kk][tx * 8];
            float4 b1 = *(const float4*)&Bs[kk][tx * 8 + 4];
            float ra[8] = {a0.x, a0.y, a0.z, a0.w, a1.x, a1.y, a1.z, a1.w};
            float rb[8] = {b0.x, b0.y, b0.z, b0.w, b1.x, b1.y, b1.z, b1.w};
            #pragma unroll
            for (int i = 0; i < 8; i++)
                #pragma unroll
                for (int j = 0; j < 8; j++)
                    acc[i][j] = fmaf(ra[i], rb[j], acc[i][j]);
        }
        __syncthreads();
    }

    // epilogue: bias + store
    #pragma unroll
    for (int i = 0; i < 8; i++) {
        int r = brow + ty * 8 + i;
        #pragma unroll
        for (int j = 0; j < 8; j += 4) {
            int cc = bcol + tx * 8 + j;
            float4 o;
            o.x = acc[i][j + 0] + bias[cc + 0];
            o.y = acc[i][j + 1] + bias[cc + 1];
            o.z = acc[i][j + 2] + bias[cc + 2];
            o.w = acc[i][j + 3] + bias[cc + 3];
            *(float4*)&C[(size_t)r * N + cc] = o;
        }
    }
}

// ======================= Flash attention (fp32) =============================
// One block handles a 64-row Q tile of one (b,h). 256 threads, 16x16 grid;
// thread owns rows {i*16+ty}, cols {j*16+tx} of the 64x64 S / O tiles.
#define AP 65   // smem row pad (floats)

__global__ __launch_bounds__(256)
void flash_attn_kernel(const float* __restrict__ q,
                       const float* __restrict__ kv,
                       float* __restrict__ vals)
{
    extern __shared__ float sm[];
    float* Qs  = sm;                 // [64][AP]
    float* Ks  = Qs + 64 * AP;       // [64][AP]
    float* Vs  = Ks + 64 * AP;       // [64][AP]
    float* Ss  = Vs + 64 * AP;       // [64][AP]
    float* m_s = Ss + 64 * AP;       // [64]
    float* l_s = m_s + 64;           // [64]
    float* a_s = l_s + 64;           // [64]

    const int tid = threadIdx.x;
    const int ty = tid >> 4, tx = tid & 15;
    const int b  = blockIdx.y >> 4;
    const int h  = blockIdx.y & 15;
    const int q0 = blockIdx.x * 64;

    const float* qbase = q  + ((size_t)b * SEQ + q0) * EMB + h * HD;
    const float* kbase = kv + (size_t)b * SEQ * (2 * EMB) + h * (2 * HD);

    // load Q tile, pre-scaled by 1/sqrt(64)
    #pragma unroll
    for (int i = 0; i < 4; i++) {
        int idx = tid + i * 256;
        int r = idx >> 4, d4 = (idx & 15) * 4;
        float4 v = *(const float4*)(qbase + (size_t)r * EMB + d4);
        Qs[r * AP + d4 + 0] = v.x * 0.125f;
        Qs[r * AP + d4 + 1] = v.y * 0.125f;
        Qs[r * AP + d4 + 2] = v.z * 0.125f;
        Qs[r * AP + d4 + 3] = v.w * 0.125f;
    }
    if (tid < 64) { m_s[tid] = __int_as_float(0xff800000); l_s[tid] = 0.f; }

    float o[4][4];
    #pragma unroll
    for (int i = 0; i < 4; i++)
        #pragma unroll
        for (int j = 0; j < 4; j++) o[i][j] = 0.f;

    for (int s0 = 0; s0 < SEQ; s0 += 64) {
        // ---- load K,V tiles ----
        #pragma unroll
        for (int i = 0; i < 4; i++) {
            int idx = tid + i * 256;
            int r = idx >> 4, d4 = (idx & 15) * 4;
            const float* row = kbase + (size_t)(s0 + r) * (2 * EMB);
            float4 kk4 = *(const float4*)(row + d4);
            float4 vv4 = *(const float4*)(row + HD + d4);
            Ks[r * AP + d4 + 0] = kk4.x; Ks[r * AP + d4 + 1] = kk4.y;
            Ks[r * AP + d4 + 2] = kk4.z; Ks[r * AP + d4 + 3] = kk4.w;
            Vs[r * AP + d4 + 0] = vv4.x; Vs[r * AP + d4 + 1] = vv4.y;
            Vs[r * AP + d4 + 2] = vv4.z; Vs[r * AP + d4 + 3] = vv4.w;
        }
        __syncthreads();

        // ---- phase A: S = Qs @ Ks^T ----
        float s[4][4];
        #pragma unroll
        for (int i = 0; i < 4; i++)
            #pragma unroll
            for (int j = 0; j < 4; j++) s[i][j] = 0.f;
        #pragma unroll 8
        for (int kk = 0; kk < HD; kk++) {
            float qr[4], kr[4];
            #pragma unroll
            for (int i = 0; i < 4; i++) qr[i] = Qs[(i * 16 + ty) * AP + kk];
            #pragma unroll
            for (int j = 0; j < 4; j++) kr[j] = Ks[(j * 16 + tx) * AP + kk];
            #pragma unroll
            for (int i = 0; i < 4; i++)
                #pragma unroll
                for (int j = 0; j < 4; j++)
                    s[i][j] = fmaf(qr[i], kr[j], s[i][j]);
        }
        #pragma unroll
        for (int i = 0; i < 4; i++)
            #pragma unroll
            for (int j = 0; j < 4; j++)
                Ss[(i * 16 + ty) * AP + j * 16 + tx] = s[i][j];
        __syncthreads();

        // ---- phase B: online softmax (one thread per row) ----
        if (tid < 64) {
            float* srow = Ss + tid * AP;
            float mold = m_s[tid];
            float mx = mold;
            #pragma unroll 8
            for (int cx = 0; cx < 64; cx++) mx = fmaxf(mx, srow[cx]);
            float alpha = __expf(mold - mx);
            float sum = 0.f;
            #pragma unroll 8
            for (int cx = 0; cx < 64; cx++) {
                float p = __expf(srow[cx] - mx);
                srow[cx] = p;
                sum += p;
            }
            m_s[tid] = mx;
            l_s[tid] = l_s[tid] * alpha + sum;
            a_s[tid] = alpha;
        }
        __syncthreads();

        // ---- phase C: O = O*alpha + P @ V ----
        float av[4];
        #pragma unroll
        for (int i = 0; i < 4; i++) av[i] = a_s[i * 16 + ty];
        #pragma unroll
        for (int i = 0; i < 4; i++)
            #pragma unroll
            for (int j = 0; j < 4; j++) o[i][j] *= av[i];
        #pragma unroll 8
        for (int jj = 0; jj < 64; jj++) {
            float pr[4], vr[4];
            #pragma unroll
            for (int i = 0; i < 4; i++) pr[i] = Ss[(i * 16 + ty) * AP + jj];
            #pragma unroll
            for (int j = 0; j < 4; j++) vr[j] = Vs[jj * AP + j * 16 + tx];
            #pragma unroll
            for (int i = 0; i < 4; i++)
                #pragma unroll
                for (int j = 0; j < 4; j++)
                    o[i][j] = fmaf(pr[i], vr[j], o[i][j]);
        }
        __syncthreads();
    }

    // ---- epilogue: divide by l, write values in [b][sq][h*64+d] layout ----
    float linv[4];
    #pragma unroll
    for (int i = 0; i < 4; i++) linv[i] = 1.0f / l_s[i * 16 + ty];
    float* obase = vals + ((size_t)b * SEQ + q0) * EMB + h * HD;
    #pragma unroll
    for (int i = 0; i < 4; i++)
        #pragma unroll
        for (int j = 0; j < 4; j++)
            obase[(size_t)(i * 16 + ty) * EMB + j * 16 + tx] = o[i][j] * linv[i];
}

// ======================= launch =============================================
extern "C" void kernel_launch(void* const* d_in, const int* in_sizes, int n_in,
                              void* d_out, int out_size)
{
    const float* q_in = (const float*)d_in[0];
    const float* c_in = (const float*)d_in[1];
    const float* Wkv  = (const float*)d_in[2];
    const float* bkv  = (const float*)d_in[3];
    const float* Wo   = (const float*)d_in[4];
    const float* bo   = (const float*)d_in[5];
    float* out = (float*)d_out;

    float *kv_ptr = nullptr, *vals_ptr = nullptr;
    cudaGetSymbolAddress((void**)&kv_ptr, g_kv);
    cudaGetSymbolAddress((void**)&vals_ptr, g_vals);

    const int M = BATCH * SEQ;             // 8192

    // 1) kv = c @ W_kv + b_kv         [8192, 2048]
    sgemm_bias_kernel<<<dim3((2 * EMB) / GBN, M / GBM), 256>>>(
        c_in, Wkv, bkv, kv_ptr, M, 2 * EMB, EMB);

    // 2) flash attention -> values    [8192, 1024]
    size_t smem = (size_t)(4 * 64 * AP + 3 * 64) * sizeof(float);
    cudaFuncSetAttribute(flash_attn_kernel,
                         cudaFuncAttributeMaxDynamicSharedMemorySize, (int)smem);
    flash_attn_kernel<<<dim3(SEQ / 64, BATCH * NH), 256, smem>>>(
        q_in, kv_ptr, vals_ptr);

    // 3) out = values @ W_o + b_o     [8192, 1024]
    sgemm_bias_kernel<<<dim3(EMB / GBN, M / GBM), 256>>>(
        vals_ptr, Wo, bo, out, M, EMB, EMB);
}

// round 2
// speedup vs baseline: 1.5560x; 1.5560x over previous
#include <cuda_runtime.h>
#include <mma.h>
#include <cstdint>

using namespace nvcuda;

// ---------------------------------------------------------------------------
//   q    [4, 2048, 1024], c [4, 2048, 1024]
//   W_kv [1024, 2048], b_kv [2048], W_o [1024, 1024], b_o [1024]
//   out  [4, 2048, 1024] fp32
// kv row layout per (b,s): head h -> K at cols h*128..+63, V at h*128+64..+127
// ---------------------------------------------------------------------------

#define BATCH 4
#define SEQ   2048
#define EMB   1024
#define NH    16
#define HD    64

__device__ float g_kv[(size_t)BATCH * SEQ * 2 * EMB];    // 64 MB
__device__ float g_vals[(size_t)BATCH * SEQ * EMB];      // 32 MB

// ======================= tf32 wmma SGEMM + bias =============================
// C[M,N] = A[M,K] @ B[K,N] + bias[N].  M%128==0, N%128==0, K%16==0.
#define BM 128
#define BN 128
#define BK 16
#define LDA 24     // BK + 8 pad, multiple of 8
#define LDB 136    // BN + 8 pad, multiple of 8

__global__ __launch_bounds__(256)
void gemm_tf32_bias(const float* __restrict__ A, const float* __restrict__ B,
                    const float* __restrict__ bias, float* __restrict__ C,
                    int M, int N, int K)
{
    __shared__ float As[BM * LDA];
    __shared__ float Bs[BK * LDB];
    __shared__ float BiasS[16 * LDB];

    const int tid  = threadIdx.x;
    const int w    = tid >> 5;           // warp 0..7
    const int wm   = w >> 2;             // 0..1  (64-row strip)
    const int wn   = w & 3;              // 0..3  (32-col strip)
    const int brow = blockIdx.y * BM;
    const int bcol = blockIdx.x * BN;

    // ---- bias -> replicated 16-row tile, then into accumulators ----
    #pragma unroll
    for (int i = 0; i < 8; i++) {
        int e = tid + i * 256;           // 0..2047
        int r = e >> 7, cc = e & 127;
        BiasS[r * LDB + cc] = bias[bcol + cc];
    }
    __syncthreads();

    wmma::fragment<wmma::accumulator, 16, 16, 8, float> acc[4][2];
    {
        wmma::fragment<wmma::accumulator, 16, 16, 8, float> bf[2];
        #pragma unroll
        for (int j = 0; j < 2; j++)
            wmma::load_matrix_sync(bf[j], &BiasS[wn * 32 + j * 16], LDB,
                                   wmma::mem_row_major);
        #pragma unroll
        for (int i = 0; i < 4; i++)
            #pragma unroll
            for (int j = 0; j < 2; j++) acc[i][j] = bf[j];
    }
    __syncthreads();

    const int a_row = tid >> 2;          // 0..63
    const int a_c4  = (tid & 3) * 4;
    const int b_row = tid >> 5;          // 0..7
    const int b_c4  = (tid & 31) * 4;

    for (int k0 = 0; k0 < K; k0 += BK) {
        // A tile 128x16 (row-major, tf32-rounded)
        #pragma unroll
        for (int i = 0; i < 2; i++) {
            int r = a_row + i * 64;
            float4 v = *(const float4*)&A[(size_t)(brow + r) * K + k0 + a_c4];
            float* d = &As[r * LDA + a_c4];
            d[0] = wmma::__float_to_tf32(v.x);
            d[1] = wmma::__float_to_tf32(v.y);
            d[2] = wmma::__float_to_tf32(v.z);
            d[3] = wmma::__float_to_tf32(v.w);
        }
        // B tile 16x128
        #pragma unroll
        for (int i = 0; i < 2; i++) {
            int r = b_row + i * 8;
            float4 v = *(const float4*)&B[(size_t)(k0 + r) * N + bcol + b_c4];
            float* d = &Bs[r * LDB + b_c4];
            d[0] = wmma::__float_to_tf32(v.x);
            d[1] = wmma::__float_to_tf32(v.y);
            d[2] = wmma::__float_to_tf32(v.z);
            d[3] = wmma::__float_to_tf32(v.w);
        }
        __syncthreads();

        #pragma unroll
        for (int ks = 0; ks < BK; ks += 8) {
            wmma::fragment<wmma::matrix_a, 16, 16, 8, wmma::precision::tf32,
                           wmma::row_major> af[4];
            wmma::fragment<wmma::matrix_b, 16, 16, 8, wmma::precision::tf32,
                           wmma::row_major> bfr[2];
            #pragma unroll
            for (int i = 0; i < 4; i++)
                wmma::load_matrix_sync(af[i],
                    &As[(wm * 64 + i * 16) * LDA + ks], LDA);
            #pragma unroll
            for (int j = 0; j < 2; j++)
                wmma::load_matrix_sync(bfr[j],
                    &Bs[ks * LDB + wn * 32 + j * 16], LDB);
            #pragma unroll
            for (int i = 0; i < 4; i++)
                #pragma unroll
                for (int j = 0; j < 2; j++)
                    wmma::mma_sync(acc[i][j], af[i], bfr[j], acc[i][j]);
        }
        __syncthreads();
    }

    #pragma unroll
    for (int i = 0; i < 4; i++)
        #pragma unroll
        for (int j = 0; j < 2; j++)
            wmma::store_matrix_sync(
                &C[(size_t)(brow + wm * 64 + i * 16) * N + bcol + wn * 32 + j * 16],
                acc[i][j], N, wmma::mem_row_major);
}

// ======================= Flash attention (tf32 wmma) ========================
// Block: 64-row Q tile of one (b,h). 256 threads = 8 warps.
// Warp w: S/O tile row tr = w>>1 (16 rows), tile cols {(w&1)*2, (w&1)*2+1}.
#define LDT 72     // 64 + 8 pad

__global__ __launch_bounds__(256)
void flash_attn_tf32(const float* __restrict__ q,
                     const float* __restrict__ kv,
                     float* __restrict__ vals)
{
    extern __shared__ float sm[];
    float* Qs  = sm;                  // [64][LDT]
    float* Ks  = Qs  + 64 * LDT;
    float* Vs  = Ks  + 64 * LDT;
    float* Ss  = Vs  + 64 * LDT;
    float* PVs = Ss  + 64 * LDT;
    float* m_s = PVs + 64 * LDT;      // [64]
    float* l_s = m_s + 64;
    float* a_s = l_s + 64;

    const int tid = threadIdx.x;
    const int w   = tid >> 5;
    const int tr  = w >> 1;            // 0..3
    const int tc0 = (w & 1) * 2;       // 0 or 2
    const int b   = blockIdx.y >> 4;
    const int h   = blockIdx.y & 15;
    const int q0  = blockIdx.x * 64;

    const float* qbase = q  + ((size_t)b * SEQ + q0) * EMB + h * HD;
    const float* kbase = kv + (size_t)b * SEQ * (2 * EMB) + h * (2 * HD);

    // ---- load Q tile (scaled, tf32-rounded) ----
    #pragma unroll
    for (int i = 0; i < 4; i++) {
        int idx = tid + i * 256;
        int r = idx >> 4, d4 = (idx & 15) * 4;
        float4 v = *(const float4*)(qbase + (size_t)r * EMB + d4);
        float* d = &Qs[r * LDT + d4];
        d[0] = wmma::__float_to_tf32(v.x * 0.125f);
        d[1] = wmma::__float_to_tf32(v.y * 0.125f);
        d[2] = wmma::__float_to_tf32(v.z * 0.125f);
        d[3] = wmma::__float_to_tf32(v.w * 0.125f);
    }
    if (tid < 64) { m_s[tid] = __int_as_float(0xff800000); l_s[tid] = 0.f; }
    __syncthreads();

    // ---- preload Q fragments (fixed for whole block) ----
    wmma::fragment<wmma::matrix_a, 16, 16, 8, wmma::precision::tf32,
                   wmma::row_major> qf[8];
    #pragma unroll
    for (int ks = 0; ks < 8; ks++)
        wmma::load_matrix_sync(qf[ks], &Qs[(tr * 16) * LDT + ks * 8], LDT);

    // O registers: thread owns row (tid>>2), cols (tid&3)*16 .. +15
    const int orow = tid >> 2;
    const int ocol = (tid & 3) * 16;
    float o[16];
    #pragma unroll
    for (int j = 0; j < 16; j++) o[j] = 0.f;

    for (int s0 = 0; s0 < SEQ; s0 += 64) {
        // ---- load K,V tiles (tf32-rounded) ----
        #pragma unroll
        for (int i = 0; i < 4; i++) {
            int idx = tid + i * 256;
            int r = idx >> 4, d4 = (idx & 15) * 4;
            const float* row = kbase + (size_t)(s0 + r) * (2 * EMB);
            float4 kk4 = *(const float4*)(row + d4);
            float4 vv4 = *(const float4*)(row + HD + d4);
            float* dk = &Ks[r * LDT + d4];
            float* dv = &Vs[r * LDT + d4];
            dk[0] = wmma::__float_to_tf32(kk4.x);
            dk[1] = wmma::__float_to_tf32(kk4.y);
            dk[2] = wmma::__float_to_tf32(kk4.z);
            dk[3] = wmma::__float_to_tf32(kk4.w);
            dv[0] = wmma::__float_to_tf32(vv4.x);
            dv[1] = wmma::__float_to_tf32(vv4.y);
            dv[2] = wmma::__float_to_tf32(vv4.z);
            dv[3] = wmma::__float_to_tf32(vv4.w);
        }
        __syncthreads();

        // ---- S = Q @ K^T ----
        {
            wmma::fragment<wmma::accumulator, 16, 16, 8, float> sacc[2];
            #pragma unroll
            for (int j = 0; j < 2; j++) wmma::fill_fragment(sacc[j], 0.f);
            #pragma unroll
            for (int ks = 0; ks < 8; ks++) {
                wmma::fragment<wmma::matrix_b, 16, 16, 8, wmma::precision::tf32,
                               wmma::col_major> kf[2];
                #pragma unroll
                for (int j = 0; j < 2; j++)
                    wmma::load_matrix_sync(kf[j],
                        &Ks[((tc0 + j) * 16) * LDT + ks * 8], LDT);
                #pragma unroll
                for (int j = 0; j < 2; j++)
                    wmma::mma_sync(sacc[j], qf[ks], kf[j], sacc[j]);
            }
            #pragma unroll
            for (int j = 0; j < 2; j++)
                wmma::store_matrix_sync(
                    &Ss[(tr * 16) * LDT + (tc0 + j) * 16], sacc[j], LDT,
                    wmma::mem_row_major);
        }
        __syncthreads();

        // ---- online softmax (thread t < 64 owns row t) ----
        if (tid < 64) {
            float* srow = Ss + tid * LDT;
            float mold = m_s[tid];
            float mx = mold;
            #pragma unroll 8
            for (int cx = 0; cx < 64; cx++) mx = fmaxf(mx, srow[cx]);
            float alpha = __expf(mold - mx);
            float sum = 0.f;
            #pragma unroll 8
            for (int cx = 0; cx < 64; cx++) {
                float p = __expf(srow[cx] - mx);
                srow[cx] = wmma::__float_to_tf32(p);
                sum += p;
            }
            m_s[tid] = mx;
            l_s[tid] = l_s[tid] * alpha + sum;
            a_s[tid] = alpha;
        }
        __syncthreads();

        // ---- PV = P @ V ----
        {
            wmma::fragment<wmma::accumulator, 16, 16, 8, float> oacc[2];
            #pragma unroll
            for (int j = 0; j < 2; j++) wmma::fill_fragment(oacc[j], 0.f);
            #pragma unroll
            for (int ks = 0; ks < 8; ks++) {
                wmma::fragment<wmma::matrix_a, 16, 16, 8, wmma::precision::tf32,
                               wmma::row_major> pf;
                wmma::load_matrix_sync(pf, &Ss[(tr * 16) * LDT + ks * 8], LDT);
                wmma::fragment<wmma::matrix_b, 16, 16, 8, wmma::precision::tf32,
                               wmma::row_major> vf[2];
                #pragma unroll
                for (int j = 0; j < 2; j++)
                    wmma::load_matrix_sync(vf[j],
                        &Vs[(ks * 8) * LDT + (tc0 + j) * 16], LDT);
                #pragma unroll
                for (int j = 0; j < 2; j++)
                    wmma::mma_sync(oacc[j], pf, vf[j], oacc[j]);
            }
            #pragma unroll
            for (int j = 0; j < 2; j++)
                wmma::store_matrix_sync(
                    &PVs[(tr * 16) * LDT + (tc0 + j) * 16], oacc[j], LDT,
                    wmma::mem_row_major);
        }
        __syncthreads();

        // ---- O = O*alpha + PV ----
        {
            float alpha = a_s[orow];
            const float* pvrow = &PVs[orow * LDT + ocol];
            #pragma unroll
            for (int j = 0; j < 16; j++)
                o[j] = fmaf(o[j], alpha, pvrow[j]);
        }
        __syncthreads();
    }

    // ---- epilogue ----
    float linv = 1.0f / l_s[orow];
    float* obase = vals + ((size_t)b * SEQ + q0 + orow) * EMB + h * HD + ocol;
    #pragma unroll
    for (int j = 0; j < 16; j++) obase[j] = o[j] * linv;
}

// ======================= launch =============================================
extern "C" void kernel_launch(void* const* d_in, const int* in_sizes, int n_in,
                              void* d_out, int out_size)
{
    const float* q_in = (const float*)d_in[0];
    const float* c_in = (const float*)d_in[1];
    const float* Wkv  = (const float*)d_in[2];
    const float* bkv  = (const float*)d_in[3];
    const float* Wo   = (const float*)d_in[4];
    const float* bo   = (const float*)d_in[5];
    float* out = (float*)d_out;

    float *kv_ptr = nullptr, *vals_ptr = nullptr;
    cudaGetSymbolAddress((void**)&kv_ptr, g_kv);
    cudaGetSymbolAddress((void**)&vals_ptr, g_vals);

    const int M = BATCH * SEQ;             // 8192

    // 1) kv = c @ W_kv + b_kv         [8192, 2048]
    gemm_tf32_bias<<<dim3((2 * EMB) / BN, M / BM), 256>>>(
        c_in, Wkv, bkv, kv_ptr, M, 2 * EMB, EMB);

    // 2) flash attention -> values    [8192, 1024]
    size_t smem = (size_t)(5 * 64 * LDT + 3 * 64) * sizeof(float);
    static int smem_set = 0;
    cudaFuncSetAttribute(flash_attn_tf32,
                         cudaFuncAttributeMaxDynamicSharedMemorySize, (int)smem);
    (void)smem_set;
    flash_attn_tf32<<<dim3(SEQ / 64, BATCH * NH), 256, smem>>>(
        q_in, kv_ptr, vals_ptr);

    // 3) out = values @ W_o + b_o     [8192, 1024]
    gemm_tf32_bias<<<dim3(EMB / BN, M / BM), 256>>>(
        vals_ptr, Wo, bo, out, M, EMB, EMB);
}

// round 3
// speedup vs baseline: 2.6592x; 1.7090x over previous
#include <cuda_runtime.h>
#include <mma.h>
#include <cstdint>

using namespace nvcuda;

// ---------------------------------------------------------------------------
//   q [4,2048,1024], c [4,2048,1024], W_kv [1024,2048], b_kv [2048],
//   W_o [1024,1024], b_o [1024] -> out [4,2048,1024] fp32
// kv row layout per (b,s): head h -> K at cols h*128..+63, V at h*128+64..+127
// ---------------------------------------------------------------------------

#define BATCH 4
#define SEQ   2048
#define EMB   1024
#define NH    16
#define HD    64

__device__ float g_kv[(size_t)BATCH * SEQ * 2 * EMB];    // 64 MB
__device__ float g_vals[(size_t)BATCH * SEQ * EMB];      // 32 MB

__device__ __forceinline__ uint32_t f2tf(float x) {
    uint32_t r;
    asm("cvt.rna.tf32.f32 %0, %1;" : "=r"(r) : "f"(x));
    return r;
}

#define MMA_TF32(d, a, b0v, b1v)                                            \
    asm volatile("mma.sync.aligned.m16n8k8.row.col.f32.tf32.tf32.f32 "      \
        "{%0,%1,%2,%3}, {%4,%5,%6,%7}, {%8,%9}, {%0,%1,%2,%3};"             \
        : "+f"((d)[0]), "+f"((d)[1]), "+f"((d)[2]), "+f"((d)[3])            \
        : "r"((a)[0]), "r"((a)[1]), "r"((a)[2]), "r"((a)[3]),               \
          "r"(b0v), "r"(b1v))

// ======================= tf32 wmma SGEMM + bias (double-buffered) ===========
#define BM 128
#define BN 128
#define BK 16
#define LDA 24
#define LDB 136

__global__ __launch_bounds__(256, 2)
void gemm_tf32_bias(const float* __restrict__ A, const float* __restrict__ B,
                    const float* __restrict__ bias, float* __restrict__ C,
                    int M, int N, int K)
{
    __shared__ float As[2][BM * LDA];
    __shared__ float Bs[2][BK * LDB];

    const int tid  = threadIdx.x;
    const int w    = tid >> 5;
    const int wm   = w >> 2;
    const int wn   = w & 3;
    const int brow = blockIdx.y * BM;
    const int bcol = blockIdx.x * BN;

    // ---- bias -> replicated 16-row tile in As[0], then into accumulators ----
    {
        float* BiasS = &As[0][0];
        #pragma unroll
        for (int i = 0; i < 8; i++) {
            int e = tid + i * 256;
            int r = e >> 7, cc = e & 127;
            BiasS[r * LDB + cc] = bias[bcol + cc];
        }
    }
    __syncthreads();

    wmma::fragment<wmma::accumulator, 16, 16, 8, float> acc[4][2];
    {
        wmma::fragment<wmma::accumulator, 16, 16, 8, float> bf[2];
        #pragma unroll
        for (int j = 0; j < 2; j++)
            wmma::load_matrix_sync(bf[j], &As[0][wn * 32 + j * 16], LDB,
                                   wmma::mem_row_major);
        #pragma unroll
        for (int i = 0; i < 4; i++)
            #pragma unroll
            for (int j = 0; j < 2; j++) acc[i][j] = bf[j];
    }
    __syncthreads();

    const int a_row = tid >> 2;
    const int a_c4  = (tid & 3) * 4;
    const int b_row = tid >> 5;
    const int b_c4  = (tid & 31) * 4;

    float4 pa0, pa1, pb0, pb1;
    // preload k0 = 0
    pa0 = *(const float4*)&A[(size_t)(brow + a_row) * K + a_c4];
    pa1 = *(const float4*)&A[(size_t)(brow + a_row + 64) * K + a_c4];
    pb0 = *(const float4*)&B[(size_t)(b_row) * N + bcol + b_c4];
    pb1 = *(const float4*)&B[(size_t)(b_row + 8) * N + bcol + b_c4];
    {
        float* d0 = &As[0][a_row * LDA + a_c4];
        d0[0]=wmma::__float_to_tf32(pa0.x); d0[1]=wmma::__float_to_tf32(pa0.y);
        d0[2]=wmma::__float_to_tf32(pa0.z); d0[3]=wmma::__float_to_tf32(pa0.w);
        float* d1 = &As[0][(a_row + 64) * LDA + a_c4];
        d1[0]=wmma::__float_to_tf32(pa1.x); d1[1]=wmma::__float_to_tf32(pa1.y);
        d1[2]=wmma::__float_to_tf32(pa1.z); d1[3]=wmma::__float_to_tf32(pa1.w);
        float* e0 = &Bs[0][b_row * LDB + b_c4];
        e0[0]=wmma::__float_to_tf32(pb0.x); e0[1]=wmma::__float_to_tf32(pb0.y);
        e0[2]=wmma::__float_to_tf32(pb0.z); e0[3]=wmma::__float_to_tf32(pb0.w);
        float* e1 = &Bs[0][(b_row + 8) * LDB + b_c4];
        e1[0]=wmma::__float_to_tf32(pb1.x); e1[1]=wmma::__float_to_tf32(pb1.y);
        e1[2]=wmma::__float_to_tf32(pb1.z); e1[3]=wmma::__float_to_tf32(pb1.w);
    }
    __syncthreads();

    const int nk = K / BK;
    for (int kt = 0; kt < nk; kt++) {
        const int s = kt & 1;
        if (kt < nk - 1) {
            int k0 = (kt + 1) * BK;
            pa0 = *(const float4*)&A[(size_t)(brow + a_row) * K + k0 + a_c4];
            pa1 = *(const float4*)&A[(size_t)(brow + a_row + 64) * K + k0 + a_c4];
            pb0 = *(const float4*)&B[(size_t)(k0 + b_row) * N + bcol + b_c4];
            pb1 = *(const float4*)&B[(size_t)(k0 + b_row + 8) * N + bcol + b_c4];
        }

        #pragma unroll
        for (int ks = 0; ks < BK; ks += 8) {
            wmma::fragment<wmma::matrix_a, 16, 16, 8, wmma::precision::tf32,
                           wmma::row_major> af[4];
            wmma::fragment<wmma::matrix_b, 16, 16, 8, wmma::precision::tf32,
                           wmma::row_major> bfr[2];
            #pragma unroll
            for (int i = 0; i < 4; i++)
                wmma::load_matrix_sync(af[i],
                    &As[s][(wm * 64 + i * 16) * LDA + ks], LDA);
            #pragma unroll
            for (int j = 0; j < 2; j++)
                wmma::load_matrix_sync(bfr[j],
                    &Bs[s][ks * LDB + wn * 32 + j * 16], LDB);
            #pragma unroll
            for (int i = 0; i < 4; i++)
                #pragma unroll
                for (int j = 0; j < 2; j++)
                    wmma::mma_sync(acc[i][j], af[i], bfr[j], acc[i][j]);
        }

        if (kt < nk - 1) {
            const int d = 1 - s;
            float* d0 = &As[d][a_row * LDA + a_c4];
            d0[0]=wmma::__float_to_tf32(pa0.x); d0[1]=wmma::__float_to_tf32(pa0.y);
            d0[2]=wmma::__float_to_tf32(pa0.z); d0[3]=wmma::__float_to_tf32(pa0.w);
            float* d1 = &As[d][(a_row + 64) * LDA + a_c4];
            d1[0]=wmma::__float_to_tf32(pa1.x); d1[1]=wmma::__float_to_tf32(pa1.y);
            d1[2]=wmma::__float_to_tf32(pa1.z); d1[3]=wmma::__float_to_tf32(pa1.w);
            float* e0 = &Bs[d][b_row * LDB + b_c4];
            e0[0]=wmma::__float_to_tf32(pb0.x); e0[1]=wmma::__float_to_tf32(pb0.y);
            e0[2]=wmma::__float_to_tf32(pb0.z); e0[3]=wmma::__float_to_tf32(pb0.w);
            float* e1 = &Bs[d][(b_row + 8) * LDB + b_c4];
            e1[0]=wmma::__float_to_tf32(pb1.x); e1[1]=wmma::__float_to_tf32(pb1.y);
            e1[2]=wmma::__float_to_tf32(pb1.z); e1[3]=wmma::__float_to_tf32(pb1.w);
        }
        __syncthreads();
    }

    #pragma unroll
    for (int i = 0; i < 4; i++)
        #pragma unroll
        for (int j = 0; j < 2; j++)
            wmma::store_matrix_sync(
                &C[(size_t)(brow + wm * 64 + i * 16) * N + bcol + wn * 32 + j * 16],
                acc[i][j], N, wmma::mem_row_major);
}

// ======================= Flash attention (raw mma, register softmax) ========
// Block: 128-row Q tile of one (b,h). 8 warps; warp w owns rows w*16..w*16+15.
// KV tile 64, double-buffered smem. K stride 68, V stride 72 (conflict-free).
#define LDK 68
#define LDV 72
#define KSZ (64 * LDK)
#define VSZ (64 * LDV)
#define STG_SZ (KSZ + VSZ)

__global__ __launch_bounds__(256)
void flash_attn_mma(const float* __restrict__ q,
                    const float* __restrict__ kv,
                    float* __restrict__ vals)
{
    extern __shared__ uint32_t smx[];
    // layout: [stage][ K(64*68) | V(64*72) ]

    const int tid  = threadIdx.x;
    const int w    = tid >> 5;
    const int lane = tid & 31;
    const int g    = lane >> 2;     // group id (row within 8)
    const int qd   = lane & 3;      // thread-in-group
    const int b    = blockIdx.y >> 4;
    const int h    = blockIdx.y & 15;
    const int q0   = blockIdx.x * 128;

    const size_t qrow0 = (size_t)b * SEQ + q0 + w * 16;
    const float* qb = q + qrow0 * EMB + h * HD;

    // ---- Q fragments (16x64 per warp), scaled + tf32 ----
    uint32_t qf[8][4];
    #pragma unroll
    for (int kk = 0; kk < 8; kk++) {
        qf[kk][0] = f2tf(qb[(size_t)g * EMB + 8 * kk + qd] * 0.125f);
        qf[kk][1] = f2tf(qb[(size_t)(g + 8) * EMB + 8 * kk + qd] * 0.125f);
        qf[kk][2] = f2tf(qb[(size_t)g * EMB + 8 * kk + qd + 4] * 0.125f);
        qf[kk][3] = f2tf(qb[(size_t)(g + 8) * EMB + 8 * kk + qd + 4] * 0.125f);
    }

    float oa[8][4];
    #pragma unroll
    for (int j = 0; j < 8; j++)
        #pragma unroll
        for (int e = 0; e < 4; e++) oa[j][e] = 0.f;
    float m0 = -1e30f, m1 = -1e30f, l0 = 0.f, l1 = 0.f;

    // KV tile loader: 64 rows x 128 cols (K|V contiguous), coalesced
    const float* kb = kv + (size_t)b * SEQ * (2 * EMB) + h * (2 * HD);
    const int r0 = tid >> 5;            // 0..7
    const int c4 = (tid & 31) * 4;      // 0..124
    float4 pv4[8];

    auto LOADT = [&](int it) {
        const float* base = kb + (size_t)(it * 64) * (2 * EMB) + c4;
        #pragma unroll
        for (int i = 0; i < 8; i++)
            pv4[i] = *(const float4*)(base + (size_t)(r0 + 8 * i) * (2 * EMB));
    };
    auto STORET = [&](int s) {
        uint32_t* Ks = smx + s * STG_SZ;
        uint32_t* Vs = Ks + KSZ;
        #pragma unroll
        for (int i = 0; i < 8; i++) {
            int r = r0 + 8 * i;
            uint4 u;
            u.x = f2tf(pv4[i].x); u.y = f2tf(pv4[i].y);
            u.z = f2tf(pv4[i].z); u.w = f2tf(pv4[i].w);
            if (c4 < 64) *(uint4*)&Ks[r * LDK + c4]        = u;
            else         *(uint4*)&Vs[r * LDV + (c4 - 64)] = u;
        }
    };

    LOADT(0);
    STORET(0);
    __syncthreads();

    const int NIT = SEQ / 64;
    for (int it = 0; it < NIT; it++) {
        const int s = it & 1;
        const uint32_t* Ks = smx + s * STG_SZ;
        const uint32_t* Vs = Ks + KSZ;

        if (it < NIT - 1) LOADT(it + 1);

        // ---- S = Q @ K^T : 8 kv n-tiles, regs only ----
        float sa[8][4];
        #pragma unroll
        for (int j = 0; j < 8; j++)
            #pragma unroll
            for (int e = 0; e < 4; e++) sa[j][e] = 0.f;
        #pragma unroll
        for (int kk = 0; kk < 8; kk++) {
            #pragma unroll
            for (int j = 0; j < 8; j++) {
                uint32_t b0 = Ks[(8 * j + g) * LDK + 8 * kk + qd];
                uint32_t b1 = Ks[(8 * j + g) * LDK + 8 * kk + qd + 4];
                MMA_TF32(sa[j], qf[kk], b0, b1);
            }
        }

        // ---- online softmax (warp-local; rows g and g+8) ----
        float tm0 = -1e30f, tm1 = -1e30f;
        #pragma unroll
        for (int j = 0; j < 8; j++) {
            tm0 = fmaxf(tm0, fmaxf(sa[j][0], sa[j][1]));
            tm1 = fmaxf(tm1, fmaxf(sa[j][2], sa[j][3]));
        }
        tm0 = fmaxf(tm0, __shfl_xor_sync(0xffffffffu, tm0, 1));
        tm0 = fmaxf(tm0, __shfl_xor_sync(0xffffffffu, tm0, 2));
        tm1 = fmaxf(tm1, __shfl_xor_sync(0xffffffffu, tm1, 1));
        tm1 = fmaxf(tm1, __shfl_xor_sync(0xffffffffu, tm1, 2));
        float mn0 = fmaxf(m0, tm0), mn1 = fmaxf(m1, tm1);
        float al0 = __expf(m0 - mn0), al1 = __expf(m1 - mn1);
        m0 = mn0; m1 = mn1;

        uint32_t pf[8][4];
        float sum0 = 0.f, sum1 = 0.f;
        #pragma unroll
        for (int j = 0; j < 8; j++) {
            float p0 = __expf(sa[j][0] - mn0);
            float p1 = __expf(sa[j][1] - mn0);
            float p2 = __expf(sa[j][2] - mn1);
            float p3 = __expf(sa[j][3] - mn1);
            sum0 += p0 + p1; sum1 += p2 + p3;
            pf[j][0] = f2tf(p0); pf[j][1] = f2tf(p1);
            pf[j][2] = f2tf(p2); pf[j][3] = f2tf(p3);
        }
        l0 = l0 * al0 + sum0;
        l1 = l1 * al1 + sum1;
        #pragma unroll
        for (int j = 0; j < 8; j++) {
            oa[j][0] *= al0; oa[j][1] *= al0;
            oa[j][2] *= al1; oa[j][3] *= al1;
        }

        // ---- O += P @ V ----
        const int srcA = (lane & ~3) | (qd >> 1);
        const int srcB = srcA + 2;
        #pragma unroll
        for (int kk = 0; kk < 8; kk++) {
            // re-layout P n-tile kk (C-frag) -> A-frag via shuffles
            uint32_t v0 = __shfl_sync(0xffffffffu, pf[kk][0], srcA);
            uint32_t v1 = __shfl_sync(0xffffffffu, pf[kk][1], srcA);
            uint32_t w0 = __shfl_sync(0xffffffffu, pf[kk][0], srcB);
            uint32_t w1 = __shfl_sync(0xffffffffu, pf[kk][1], srcB);
            uint32_t v2 = __shfl_sync(0xffffffffu, pf[kk][2], srcA);
            uint32_t v3 = __shfl_sync(0xffffffffu, pf[kk][3], srcA);
            uint32_t w2 = __shfl_sync(0xffffffffu, pf[kk][2], srcB);
            uint32_t w3 = __shfl_sync(0xffffffffu, pf[kk][3], srcB);
            uint32_t af[4];
            af[0] = (qd & 1) ? v1 : v0;
            af[2] = (qd & 1) ? w1 : w0;
            af[1] = (qd & 1) ? v3 : v2;
            af[3] = (qd & 1) ? w3 : w2;
            #pragma unroll
            for (int j = 0; j < 8; j++) {
                uint32_t b0 = Vs[(8 * kk + qd) * LDV + 8 * j + g];
                uint32_t b1 = Vs[(8 * kk + qd + 4) * LDV + 8 * j + g];
                MMA_TF32(oa[j], af, b0, b1);
            }
        }

        if (it < NIT - 1) STORET(1 - s);
        __syncthreads();
    }

    // ---- epilogue: reduce l across quad, normalize, store ----
    l0 += __shfl_xor_sync(0xffffffffu, l0, 1);
    l0 += __shfl_xor_sync(0xffffffffu, l0, 2);
    l1 += __shfl_xor_sync(0xffffffffu, l1, 1);
    l1 += __shfl_xor_sync(0xffffffffu, l1, 2);
    float li0 = 1.0f / l0, li1 = 1.0f / l1;

    float* ob = vals + qrow0 * EMB + h * HD;
    #pragma unroll
    for (int j = 0; j < 8; j++) {
        float2 x0 = make_float2(oa[j][0] * li0, oa[j][1] * li0);
        float2 x1 = make_float2(oa[j][2] * li1, oa[j][3] * li1);
        *(float2*)&ob[(size_t)g * EMB + 8 * j + 2 * qd]       = x0;
        *(float2*)&ob[(size_t)(g + 8) * EMB + 8 * j + 2 * qd] = x1;
    }
}

// ======================= launch =============================================
extern "C" void kernel_launch(void* const* d_in, const int* in_sizes, int n_in,
                              void* d_out, int out_size)
{
    const float* q_in = (const float*)d_in[0];
    const float* c_in = (const float*)d_in[1];
    const float* Wkv  = (const float*)d_in[2];
    const float* bkv  = (const float*)d_in[3];
    const float* Wo   = (const float*)d_in[4];
    const float* bo   = (const float*)d_in[5];
    float* out = (float*)d_out;

    float *kv_ptr = nullptr, *vals_ptr = nullptr;
    cudaGetSymbolAddress((void**)&kv_ptr, g_kv);
    cudaGetSymbolAddress((void**)&vals_ptr, g_vals);

    const int M = BATCH * SEQ;             // 8192

    // 1) kv = c @ W_kv + b_kv         [8192, 2048]
    gemm_tf32_bias<<<dim3((2 * EMB) / BN, M / BM), 256>>>(
        c_in, Wkv, bkv, kv_ptr, M, 2 * EMB, EMB);

    // 2) flash attention -> values    [8192, 1024]
    size_t smem = (size_t)2 * STG_SZ * sizeof(uint32_t);   // 71.7 KB
    cudaFuncSetAttribute(flash_attn_mma,
                         cudaFuncAttributeMaxDynamicSharedMemorySize, (int)smem);
    flash_attn_mma<<<dim3(SEQ / 128, BATCH * NH), 256, smem>>>(
        q_in, kv_ptr, vals_ptr);

    // 3) out = values @ W_o + b_o     [8192, 1024]
    gemm_tf32_bias<<<dim3(EMB / BN, M / BM), 256>>>(
        vals_ptr, Wo, bo, out, M, EMB, EMB);
}

// round 5
// speedup vs baseline: 3.5299x; 1.3274x over previous
#include <cuda_runtime.h>
#include <cstdint>

// ---------------------------------------------------------------------------
//   q [4,2048,1024], c [4,2048,1024], W_kv [1024,2048], b_kv [2048],
//   W_o [1024,1024], b_o [1024] -> out [4,2048,1024] fp32
// kv row layout per (b,s): head h -> K at cols h*128..+63, V at h*128+64..+127
// ---------------------------------------------------------------------------

#define BATCH 4
#define SEQ   2048
#define EMB   1024
#define NH    16
#define HD    64

__device__ float g_kv[(size_t)BATCH * SEQ * 2 * EMB];    // 64 MB
__device__ float g_vals[(size_t)BATCH * SEQ * EMB];      // 32 MB
__device__ float g_wkvt[(size_t)2 * EMB * EMB];          // 8 MB  W_kv^T [2048,1024]
__device__ float g_wot[(size_t)EMB * EMB];               // 4 MB  W_o^T  [1024,1024]

__device__ __forceinline__ uint32_t f2tf(float x) {
    uint32_t r;
    asm("cvt.rna.tf32.f32 %0, %1;" : "=r"(r) : "f"(x));
    return r;
}

#define MMA_TF32(d, a, b0v, b1v)                                            \
    asm volatile("mma.sync.aligned.m16n8k8.row.col.f32.tf32.tf32.f32 "      \
        "{%0,%1,%2,%3}, {%4,%5,%6,%7}, {%8,%9}, {%0,%1,%2,%3};"             \
        : "+f"((d)[0]), "+f"((d)[1]), "+f"((d)[2]), "+f"((d)[3])            \
        : "r"((a)[0]), "r"((a)[1]), "r"((a)[2]), "r"((a)[3]),               \
          "r"(b0v), "r"(b1v))

// ======================= weight transpose ===================================
__global__ __launch_bounds__(256)
void transpose_kernel(const float* __restrict__ in, float* __restrict__ out,
                      int R, int C)
{
    __shared__ float t[32][33];
    int bx = blockIdx.x * 32, by = blockIdx.y * 32;
    int x = bx + threadIdx.x;
    #pragma unroll
    for (int i = 0; i < 32; i += 8)
        t[threadIdx.y + i][threadIdx.x] = in[(size_t)(by + threadIdx.y + i) * C + x];
    __syncthreads();
    int ox = by + threadIdx.x;
    #pragma unroll
    for (int i = 0; i < 32; i += 8)
        out[(size_t)(bx + threadIdx.y + i) * R + ox] = t[threadIdx.x][threadIdx.y + i];
}

// ======================= raw-mma tf32 GEMM + bias ===========================
// C[M,N] = A[M,K] @ Bt[N,K]^T + bias[N].  Block 128x128, 8 warps.
// Warp w owns rows 16w..16w+15 x all 128 cols (16 n-tiles of m16n8).
// K chunked by 32, double-buffered smem, stride 36 (conflict-free).
#define GLD  36
#define GASZ (128 * GLD)          // words per buffer (A or B)
#define GSMEM (4 * GASZ * 4)      // 73728 bytes

__global__ __launch_bounds__(256, 1)
void gemm_mma_tf32(const float* __restrict__ A, const float* __restrict__ Bt,
                   const float* __restrict__ bias, float* __restrict__ C,
                   int M, int N, int K)
{
    extern __shared__ uint32_t gsm[];
    // layout: As[2][GASZ] | Bs[2][GASZ]

    const int tid  = threadIdx.x;
    const int w    = tid >> 5;
    const int lane = tid & 31;
    const int g    = lane >> 2;
    const int qd   = lane & 3;
    const int brow = blockIdx.y * 128;
    const int bcol = blockIdx.x * 128;

    float acc[16][4];
    #pragma unroll
    for (int j = 0; j < 16; j++)
        #pragma unroll
        for (int e = 0; e < 4; e++) acc[j][e] = 0.f;

    const int r0 = tid >> 3;          // 0..31
    const int c4 = (tid & 7) * 4;     // 0..28

    float4 Ar[4], Br[4];
    auto LOADT = [&](int k0) {
        #pragma unroll
        for (int i = 0; i < 4; i++) {
            Ar[i] = *(const float4*)(A  + (size_t)(brow + r0 + 32 * i) * K + k0 + c4);
            Br[i] = *(const float4*)(Bt + (size_t)(bcol + r0 + 32 * i) * K + k0 + c4);
        }
    };
    auto STORET = [&](int p) {
        uint32_t* Ab = gsm + p * GASZ;
        uint32_t* Bb = gsm + 2 * GASZ + p * GASZ;
        #pragma unroll
        for (int i = 0; i < 4; i++) {
            int off = (r0 + 32 * i) * GLD + c4;
            uint4 ua, ub;
            ua.x = f2tf(Ar[i].x); ua.y = f2tf(Ar[i].y);
            ua.z = f2tf(Ar[i].z); ua.w = f2tf(Ar[i].w);
            ub.x = f2tf(Br[i].x); ub.y = f2tf(Br[i].y);
            ub.z = f2tf(Br[i].z); ub.w = f2tf(Br[i].w);
            *(uint4*)&Ab[off] = ua;
            *(uint4*)&Bb[off] = ub;
        }
    };

    LOADT(0);
    STORET(0);
    __syncthreads();

    const int NCH = K / 32;
    for (int ch = 0; ch < NCH; ch++) {
        const int p = ch & 1;
        if (ch + 1 < NCH) LOADT((ch + 1) * 32);

        const uint32_t* Ab = gsm + p * GASZ;
        const uint32_t* Bb = gsm + 2 * GASZ + p * GASZ;
        const int arow0 = (16 * w + g) * GLD;
        const int arow1 = arow0 + 8 * GLD;

        #pragma unroll
        for (int ks = 0; ks < 4; ks++) {
            uint32_t af[4];
            af[0] = Ab[arow0 + 8 * ks + qd];
            af[1] = Ab[arow1 + 8 * ks + qd];
            af[2] = Ab[arow0 + 8 * ks + qd + 4];
            af[3] = Ab[arow1 + 8 * ks + qd + 4];
            #pragma unroll
            for (int j = 0; j < 16; j++) {
                uint32_t b0 = Bb[(8 * j + g) * GLD + 8 * ks + qd];
                uint32_t b1 = Bb[(8 * j + g) * GLD + 8 * ks + qd + 4];
                MMA_TF32(acc[j], af, b0, b1);
            }
        }

        if (ch + 1 < NCH) STORET(1 - p);
        __syncthreads();
    }

    // epilogue: bias + store (thread owns rows g,g+8; cols 2qd,2qd+1 per tile)
    const int row0 = brow + 16 * w + g;
    const int row1 = row0 + 8;
    #pragma unroll
    for (int j = 0; j < 16; j++) {
        int col = bcol + 8 * j + 2 * qd;
        float b0 = __ldg(bias + col), b1 = __ldg(bias + col + 1);
        float2 x0 = make_float2(acc[j][0] + b0, acc[j][1] + b1);
        float2 x1 = make_float2(acc[j][2] + b0, acc[j][3] + b1);
        *(float2*)&C[(size_t)row0 * N + col] = x0;
        *(float2*)&C[(size_t)row1 * N + col] = x1;
    }
}

// ======================= Flash attention (raw mma, register softmax) ========
#define LDK 68
#define LDV 72
#define KSZ (64 * LDK)
#define VSZ (64 * LDV)
#define STG_SZ (KSZ + VSZ)

__global__ __launch_bounds__(256)
void flash_attn_mma(const float* __restrict__ q,
                    const float* __restrict__ kv,
                    float* __restrict__ vals)
{
    extern __shared__ uint32_t smx[];

    const int tid  = threadIdx.x;
    const int w    = tid >> 5;
    const int lane = tid & 31;
    const int g    = lane >> 2;
    const int qd   = lane & 3;
    const int b    = blockIdx.y >> 4;
    const int h    = blockIdx.y & 15;
    const int q0   = blockIdx.x * 128;

    const size_t qrow0 = (size_t)b * SEQ + q0 + w * 16;
    const float* qb = q + qrow0 * EMB + h * HD;

    uint32_t qf[8][4];
    #pragma unroll
    for (int kk = 0; kk < 8; kk++) {
        qf[kk][0] = f2tf(qb[(size_t)g * EMB + 8 * kk + qd] * 0.125f);
        qf[kk][1] = f2tf(qb[(size_t)(g + 8) * EMB + 8 * kk + qd] * 0.125f);
        qf[kk][2] = f2tf(qb[(size_t)g * EMB + 8 * kk + qd + 4] * 0.125f);
        qf[kk][3] = f2tf(qb[(size_t)(g + 8) * EMB + 8 * kk + qd + 4] * 0.125f);
    }

    float oa[8][4];
    #pragma unroll
    for (int j = 0; j < 8; j++)
        #pragma unroll
        for (int e = 0; e < 4; e++) oa[j][e] = 0.f;
    float m0 = -1e30f, m1 = -1e30f, l0 = 0.f, l1 = 0.f;

    const float* kb = kv + (size_t)b * SEQ * (2 * EMB) + h * (2 * HD);
    const int r0 = tid >> 5;
    const int c4 = (tid & 31) * 4;
    float4 pv4[8];

    auto LOADT = [&](int it) {
        const float* base = kb + (size_t)(it * 64) * (2 * EMB) + c4;
        #pragma unroll
        for (int i = 0; i < 8; i++)
            pv4[i] = *(const float4*)(base + (size_t)(r0 + 8 * i) * (2 * EMB));
    };
    auto STORET = [&](int s) {
        uint32_t* Ks = smx + s * STG_SZ;
        uint32_t* Vs = Ks + KSZ;
        #pragma unroll
        for (int i = 0; i < 8; i++) {
            int r = r0 + 8 * i;
            uint4 u;
            u.x = f2tf(pv4[i].x); u.y = f2tf(pv4[i].y);
            u.z = f2tf(pv4[i].z); u.w = f2tf(pv4[i].w);
            if (c4 < 64) *(uint4*)&Ks[r * LDK + c4]        = u;
            else         *(uint4*)&Vs[r * LDV + (c4 - 64)] = u;
        }
    };

    LOADT(0);
    STORET(0);
    __syncthreads();

    const int NIT = SEQ / 64;
    for (int it = 0; it < NIT; it++) {
        const int s = it & 1;
        const uint32_t* Ks = smx + s * STG_SZ;
        const uint32_t* Vs = Ks + KSZ;

        if (it < NIT - 1) LOADT(it + 1);

        float sa[8][4];
        #pragma unroll
        for (int j = 0; j < 8; j++)
            #pragma unroll
            for (int e = 0; e < 4; e++) sa[j][e] = 0.f;
        #pragma unroll
        for (int kk = 0; kk < 8; kk++) {
            #pragma unroll
            for (int j = 0; j < 8; j++) {
                uint32_t b0 = Ks[(8 * j + g) * LDK + 8 * kk + qd];
                uint32_t b1 = Ks[(8 * j + g) * LDK + 8 * kk + qd + 4];
                MMA_TF32(sa[j], qf[kk], b0, b1);
            }
        }

        float tm0 = -1e30f, tm1 = -1e30f;
        #pragma unroll
        for (int j = 0; j < 8; j++) {
            tm0 = fmaxf(tm0, fmaxf(sa[j][0], sa[j][1]));
            tm1 = fmaxf(tm1, fmaxf(sa[j][2], sa[j][3]));
        }
        tm0 = fmaxf(tm0, __shfl_xor_sync(0xffffffffu, tm0, 1));
        tm0 = fmaxf(tm0, __shfl_xor_sync(0xffffffffu, tm0, 2));
        tm1 = fmaxf(tm1, __shfl_xor_sync(0xffffffffu, tm1, 1));
        tm1 = fmaxf(tm1, __shfl_xor_sync(0xffffffffu, tm1, 2));
        float mn0 = fmaxf(m0, tm0), mn1 = fmaxf(m1, tm1);
        float al0 = __expf(m0 - mn0), al1 = __expf(m1 - mn1);
        m0 = mn0; m1 = mn1;

        uint32_t pf[8][4];
        float sum0 = 0.f, sum1 = 0.f;
        #pragma unroll
        for (int j = 0; j < 8; j++) {
            float p0 = __expf(sa[j][0] - mn0);
            float p1 = __expf(sa[j][1] - mn0);
            float p2 = __expf(sa[j][2] - mn1);
            float p3 = __expf(sa[j][3] - mn1);
            sum0 += p0 + p1; sum1 += p2 + p3;
            pf[j][0] = f2tf(p0); pf[j][1] = f2tf(p1);
            pf[j][2] = f2tf(p2); pf[j][3] = f2tf(p3);
        }
        l0 = l0 * al0 + sum0;
        l1 = l1 * al1 + sum1;
        #pragma unroll
        for (int j = 0; j < 8; j++) {
            oa[j][0] *= al0; oa[j][1] *= al0;
            oa[j][2] *= al1; oa[j][3] *= al1;
        }

        const int srcA = (lane & ~3) | (qd >> 1);
        const int srcB = srcA + 2;
        #pragma unroll
        for (int kk = 0; kk < 8; kk++) {
            uint32_t v0 = __shfl_sync(0xffffffffu, pf[kk][0], srcA);
            uint32_t v1 = __shfl_sync(0xffffffffu, pf[kk][1], srcA);
            uint32_t w0 = __shfl_sync(0xffffffffu, pf[kk][0], srcB);
            uint32_t w1 = __shfl_sync(0xffffffffu, pf[kk][1], srcB);
            uint32_t v2 = __shfl_sync(0xffffffffu, pf[kk][2], srcA);
            uint32_t v3 = __shfl_sync(0xffffffffu, pf[kk][3], srcA);
            uint32_t w2 = __shfl_sync(0xffffffffu, pf[kk][2], srcB);
            uint32_t w3 = __shfl_sync(0xffffffffu, pf[kk][3], srcB);
            uint32_t af[4];
            af[0] = (qd & 1) ? v1 : v0;
            af[2] = (qd & 1) ? w1 : w0;
            af[1] = (qd & 1) ? v3 : v2;
            af[3] = (qd & 1) ? w3 : w2;
            #pragma unroll
            for (int j = 0; j < 8; j++) {
                uint32_t b0 = Vs[(8 * kk + qd) * LDV + 8 * j + g];
                uint32_t b1 = Vs[(8 * kk + qd + 4) * LDV + 8 * j + g];
                MMA_TF32(oa[j], af, b0, b1);
            }
        }

        if (it < NIT - 1) STORET(1 - s);
        __syncthreads();
    }

    l0 += __shfl_xor_sync(0xffffffffu, l0, 1);
    l0 += __shfl_xor_sync(0xffffffffu, l0, 2);
    l1 += __shfl_xor_sync(0xffffffffu, l1, 1);
    l1 += __shfl_xor_sync(0xffffffffu, l1, 2);
    float li0 = 1.0f / l0, li1 = 1.0f / l1;

    float* ob = vals + qrow0 * EMB + h * HD;
    #pragma unroll
    for (int j = 0; j < 8; j++) {
        float2 x0 = make_float2(oa[j][0] * li0, oa[j][1] * li0);
        float2 x1 = make_float2(oa[j][2] * li1, oa[j][3] * li1);
        *(float2*)&ob[(size_t)g * EMB + 8 * j + 2 * qd]       = x0;
        *(float2*)&ob[(size_t)(g + 8) * EMB + 8 * j + 2 * qd] = x1;
    }
}

// ======================= launch =============================================
extern "C" void kernel_launch(void* const* d_in, const int* in_sizes, int n_in,
                              void* d_out, int out_size)
{
    const float* q_in = (const float*)d_in[0];
    const float* c_in = (const float*)d_in[1];
    const float* Wkv  = (const float*)d_in[2];
    const float* bkv  = (const float*)d_in[3];
    const float* Wo   = (const float*)d_in[4];
    const float* bo   = (const float*)d_in[5];
    float* out = (float*)d_out;

    float *kv_ptr, *vals_ptr, *wkvt_ptr, *wot_ptr;
    cudaGetSymbolAddress((void**)&kv_ptr,  g_kv);
    cudaGetSymbolAddress((void**)&vals_ptr, g_vals);
    cudaGetSymbolAddress((void**)&wkvt_ptr, g_wkvt);
    cudaGetSymbolAddress((void**)&wot_ptr,  g_wot);

    const int M = BATCH * SEQ;             // 8192

    // 0) transpose weights
    transpose_kernel<<<dim3((2 * EMB) / 32, EMB / 32), dim3(32, 8)>>>(
        Wkv, wkvt_ptr, EMB, 2 * EMB);
    transpose_kernel<<<dim3(EMB / 32, EMB / 32), dim3(32, 8)>>>(
        Wo, wot_ptr, EMB, EMB);

    // 1) kv = c @ W_kv + b_kv         [8192, 2048]
    cudaFuncSetAttribute(gemm_mma_tf32,
                         cudaFuncAttributeMaxDynamicSharedMemorySize, GSMEM);
    gemm_mma_tf32<<<dim3((2 * EMB) / 128, M / 128), 256, GSMEM>>>(
        c_in, wkvt_ptr, bkv, kv_ptr, M, 2 * EMB, EMB);

    // 2) flash attention -> values    [8192, 1024]
    size_t smem = (size_t)2 * STG_SZ * sizeof(uint32_t);
    cudaFuncSetAttribute(flash_attn_mma,
                         cudaFuncAttributeMaxDynamicSharedMemorySize, (int)smem);
    flash_attn_mma<<<dim3(SEQ / 128, BATCH * NH), 256, smem>>>(
        q_in, kv_ptr, vals_ptr);

    // 3) out = values @ W_o + b_o     [8192, 1024]
    gemm_mma_tf32<<<dim3(EMB / 128, M / 128), 256, GSMEM>>>(
        vals_ptr, wot_ptr, bo, out, M, EMB, EMB);
}

// round 6
// speedup vs baseline: 3.6946x; 1.0467x over previous
#include <cuda_runtime.h>
#include <cstdint>

// ---------------------------------------------------------------------------
//   q [4,2048,1024], c [4,2048,1024], W_kv [1024,2048], b_kv [2048],
//   W_o [1024,1024], b_o [1024] -> out [4,2048,1024] fp32
// kv row layout per (b,s): head h -> K at cols h*128..+63, V at h*128+64..+127
// ---------------------------------------------------------------------------

#define BATCH 4
#define SEQ   2048
#define EMB   1024
#define NH    16
#define HD    64

__device__ float g_kv[(size_t)BATCH * SEQ * 2 * EMB];    // 64 MB
__device__ float g_vals[(size_t)BATCH * SEQ * EMB];      // 32 MB
__device__ float g_wkvt[(size_t)2 * EMB * EMB];          // 8 MB  W_kv^T [2048,1024]
__device__ float g_wot[(size_t)EMB * EMB];               // 4 MB  W_o^T  [1024,1024]

__device__ __forceinline__ uint32_t f2tf(float x) {
    uint32_t r;
    asm("cvt.rna.tf32.f32 %0, %1;" : "=r"(r) : "f"(x));
    return r;
}
__device__ __forceinline__ float ex2f(float x) {
    float y;
    asm("ex2.approx.f32 %0, %1;" : "=f"(y) : "f"(x));
    return y;
}

#define MMA_TF32(d, a, b0v, b1v)                                            \
    asm volatile("mma.sync.aligned.m16n8k8.row.col.f32.tf32.tf32.f32 "      \
        "{%0,%1,%2,%3}, {%4,%5,%6,%7}, {%8,%9}, {%0,%1,%2,%3};"             \
        : "+f"((d)[0]), "+f"((d)[1]), "+f"((d)[2]), "+f"((d)[3])            \
        : "r"((a)[0]), "r"((a)[1]), "r"((a)[2]), "r"((a)[3]),               \
          "r"(b0v), "r"(b1v))

// ======================= weight transpose ===================================
__global__ __launch_bounds__(256)
void transpose_kernel(const float* __restrict__ in, float* __restrict__ out,
                      int R, int C)
{
    __shared__ float t[32][33];
    int bx = blockIdx.x * 32, by = blockIdx.y * 32;
    int x = bx + threadIdx.x;
    #pragma unroll
    for (int i = 0; i < 32; i += 8)
        t[threadIdx.y + i][threadIdx.x] = in[(size_t)(by + threadIdx.y + i) * C + x];
    __syncthreads();
    int ox = by + threadIdx.x;
    #pragma unroll
    for (int i = 0; i < 32; i += 8)
        out[(size_t)(bx + threadIdx.y + i) * R + ox] = t[threadIdx.x][threadIdx.y + i];
}

// ======================= raw-mma tf32 GEMM + bias (unchanged) ===============
#define GLD  36
#define GASZ (128 * GLD)
#define GSMEM (4 * GASZ * 4)

__global__ __launch_bounds__(256, 1)
void gemm_mma_tf32(const float* __restrict__ A, const float* __restrict__ Bt,
                   const float* __restrict__ bias, float* __restrict__ C,
                   int M, int N, int K)
{
    extern __shared__ uint32_t gsm[];

    const int tid  = threadIdx.x;
    const int w    = tid >> 5;
    const int lane = tid & 31;
    const int g    = lane >> 2;
    const int qd   = lane & 3;
    const int brow = blockIdx.y * 128;
    const int bcol = blockIdx.x * 128;

    float acc[16][4];
    #pragma unroll
    for (int j = 0; j < 16; j++)
        #pragma unroll
        for (int e = 0; e < 4; e++) acc[j][e] = 0.f;

    const int r0 = tid >> 3;
    const int c4 = (tid & 7) * 4;

    float4 Ar[4], Br[4];
    auto LOADT = [&](int k0) {
        #pragma unroll
        for (int i = 0; i < 4; i++) {
            Ar[i] = *(const float4*)(A  + (size_t)(brow + r0 + 32 * i) * K + k0 + c4);
            Br[i] = *(const float4*)(Bt + (size_t)(bcol + r0 + 32 * i) * K + k0 + c4);
        }
    };
    auto STORET = [&](int p) {
        uint32_t* Ab = gsm + p * GASZ;
        uint32_t* Bb = gsm + 2 * GASZ + p * GASZ;
        #pragma unroll
        for (int i = 0; i < 4; i++) {
            int off = (r0 + 32 * i) * GLD + c4;
            uint4 ua, ub;
            ua.x = f2tf(Ar[i].x); ua.y = f2tf(Ar[i].y);
            ua.z = f2tf(Ar[i].z); ua.w = f2tf(Ar[i].w);
            ub.x = f2tf(Br[i].x); ub.y = f2tf(Br[i].y);
            ub.z = f2tf(Br[i].z); ub.w = f2tf(Br[i].w);
            *(uint4*)&Ab[off] = ua;
            *(uint4*)&Bb[off] = ub;
        }
    };

    LOADT(0);
    STORET(0);
    __syncthreads();

    const int NCH = K / 32;
    for (int ch = 0; ch < NCH; ch++) {
        const int p = ch & 1;
        if (ch + 1 < NCH) LOADT((ch + 1) * 32);

        const uint32_t* Ab = gsm + p * GASZ;
        const uint32_t* Bb = gsm + 2 * GASZ + p * GASZ;
        const int arow0 = (16 * w + g) * GLD;
        const int arow1 = arow0 + 8 * GLD;

        #pragma unroll
        for (int ks = 0; ks < 4; ks++) {
            uint32_t af[4];
            af[0] = Ab[arow0 + 8 * ks + qd];
            af[1] = Ab[arow1 + 8 * ks + qd];
            af[2] = Ab[arow0 + 8 * ks + qd + 4];
            af[3] = Ab[arow1 + 8 * ks + qd + 4];
            #pragma unroll
            for (int j = 0; j < 16; j++) {
                uint32_t b0 = Bb[(8 * j + g) * GLD + 8 * ks + qd];
                uint32_t b1 = Bb[(8 * j + g) * GLD + 8 * ks + qd + 4];
                MMA_TF32(acc[j], af, b0, b1);
            }
        }

        if (ch + 1 < NCH) STORET(1 - p);
        __syncthreads();
    }

    const int row0 = brow + 16 * w + g;
    const int row1 = row0 + 8;
    #pragma unroll
    for (int j = 0; j < 16; j++) {
        int col = bcol + 8 * j + 2 * qd;
        float b0 = __ldg(bias + col), b1 = __ldg(bias + col + 1);
        float2 x0 = make_float2(acc[j][0] + b0, acc[j][1] + b1);
        float2 x1 = make_float2(acc[j][2] + b0, acc[j][3] + b1);
        *(float2*)&C[(size_t)row0 * N + col] = x0;
        *(float2*)&C[(size_t)row1 * N + col] = x1;
    }
}

// ======================= Flash attention (KV tile 32, 2 CTAs/SM) ============
// Block: 128-row Q tile of one (b,h). 8 warps; warp w owns rows w*16..w*16+15.
// KV tile 32 rows, double-buffered. Softmax in exp2 domain (log2e folded in Q).
#define LDK 68
#define LDV 72
#define KSZ (32 * LDK)
#define VSZ (32 * LDV)
#define STG_SZ (KSZ + VSZ)

__global__ __launch_bounds__(256, 2)
void flash_attn_mma(const float* __restrict__ q,
                    const float* __restrict__ kv,
                    float* __restrict__ vals)
{
    extern __shared__ uint32_t smx[];

    const int tid  = threadIdx.x;
    const int w    = tid >> 5;
    const int lane = tid & 31;
    const int g    = lane >> 2;
    const int qd   = lane & 3;
    const int b    = blockIdx.y >> 4;
    const int h    = blockIdx.y & 15;
    const int q0   = blockIdx.x * 128;

    const size_t qrow0 = (size_t)b * SEQ + q0 + w * 16;
    const float* qb = q + qrow0 * EMB + h * HD;

    // Q fragments, scaled by 1/8 * log2(e)  (softmax runs in exp2 domain)
    const float QS = 0.125f * 1.4426950408889634f;
    uint32_t qf[8][4];
    #pragma unroll
    for (int kk = 0; kk < 8; kk++) {
        qf[kk][0] = f2tf(qb[(size_t)g * EMB + 8 * kk + qd] * QS);
        qf[kk][1] = f2tf(qb[(size_t)(g + 8) * EMB + 8 * kk + qd] * QS);
        qf[kk][2] = f2tf(qb[(size_t)g * EMB + 8 * kk + qd + 4] * QS);
        qf[kk][3] = f2tf(qb[(size_t)(g + 8) * EMB + 8 * kk + qd + 4] * QS);
    }

    float oa[8][4];
    #pragma unroll
    for (int j = 0; j < 8; j++)
        #pragma unroll
        for (int e = 0; e < 4; e++) oa[j][e] = 0.f;
    float m0 = -1e30f, m1 = -1e30f, l0 = 0.f, l1 = 0.f;

    const float* kb = kv + (size_t)b * SEQ * (2 * EMB) + h * (2 * HD);
    const int r0 = tid >> 5;            // 0..7
    const int c4 = (tid & 31) * 4;      // 0..124
    float4 pv4[4];

    auto LOADT = [&](int it) {
        const float* base = kb + (size_t)(it * 32) * (2 * EMB) + c4;
        #pragma unroll
        for (int i = 0; i < 4; i++)
            pv4[i] = *(const float4*)(base + (size_t)(r0 + 8 * i) * (2 * EMB));
    };
    auto STORET = [&](int s) {
        uint32_t* Ks = smx + s * STG_SZ;
        uint32_t* Vs = Ks + KSZ;
        #pragma unroll
        for (int i = 0; i < 4; i++) {
            int r = r0 + 8 * i;
            uint4 u;
            u.x = f2tf(pv4[i].x); u.y = f2tf(pv4[i].y);
            u.z = f2tf(pv4[i].z); u.w = f2tf(pv4[i].w);
            if (c4 < 64) *(uint4*)&Ks[r * LDK + c4]        = u;
            else         *(uint4*)&Vs[r * LDV + (c4 - 64)] = u;
        }
    };

    LOADT(0);
    STORET(0);
    __syncthreads();

    const int NIT = SEQ / 32;
    for (int it = 0; it < NIT; it++) {
        const int s = it & 1;
        const uint32_t* Ks = smx + s * STG_SZ;
        const uint32_t* Vs = Ks + KSZ;

        // ---- S = Q @ K^T : 4 kv n-tiles ----
        float sa[4][4];
        #pragma unroll
        for (int j = 0; j < 4; j++)
            #pragma unroll
            for (int e = 0; e < 4; e++) sa[j][e] = 0.f;
        #pragma unroll
        for (int kk = 0; kk < 8; kk++) {
            #pragma unroll
            for (int j = 0; j < 4; j++) {
                uint32_t b0 = Ks[(8 * j + g) * LDK + 8 * kk + qd];
                uint32_t b1 = Ks[(8 * j + g) * LDK + 8 * kk + qd + 4];
                MMA_TF32(sa[j], qf[kk], b0, b1);
            }
        }

        // prefetch next KV tile (short liveness)
        if (it < NIT - 1) LOADT(it + 1);

        // ---- online softmax in exp2 domain ----
        float tm0 = -1e30f, tm1 = -1e30f;
        #pragma unroll
        for (int j = 0; j < 4; j++) {
            tm0 = fmaxf(tm0, fmaxf(sa[j][0], sa[j][1]));
            tm1 = fmaxf(tm1, fmaxf(sa[j][2], sa[j][3]));
        }
        tm0 = fmaxf(tm0, __shfl_xor_sync(0xffffffffu, tm0, 1));
        tm0 = fmaxf(tm0, __shfl_xor_sync(0xffffffffu, tm0, 2));
        tm1 = fmaxf(tm1, __shfl_xor_sync(0xffffffffu, tm1, 1));
        tm1 = fmaxf(tm1, __shfl_xor_sync(0xffffffffu, tm1, 2));
        float mn0 = fmaxf(m0, tm0), mn1 = fmaxf(m1, tm1);
        float al0 = ex2f(m0 - mn0), al1 = ex2f(m1 - mn1);
        m0 = mn0; m1 = mn1;

        uint32_t pf[4][4];
        float sum0 = 0.f, sum1 = 0.f;
        #pragma unroll
        for (int j = 0; j < 4; j++) {
            float p0 = ex2f(sa[j][0] - mn0);
            float p1 = ex2f(sa[j][1] - mn0);
            float p2 = ex2f(sa[j][2] - mn1);
            float p3 = ex2f(sa[j][3] - mn1);
            sum0 += p0 + p1; sum1 += p2 + p3;
            pf[j][0] = f2tf(p0); pf[j][1] = f2tf(p1);
            pf[j][2] = f2tf(p2); pf[j][3] = f2tf(p3);
        }
        l0 = l0 * al0 + sum0;
        l1 = l1 * al1 + sum1;
        #pragma unroll
        for (int j = 0; j < 8; j++) {
            oa[j][0] *= al0; oa[j][1] *= al0;
            oa[j][2] *= al1; oa[j][3] *= al1;
        }

        // ---- O += P @ V ----
        const int srcA = (lane & ~3) | (qd >> 1);
        const int srcB = srcA + 2;
        #pragma unroll
        for (int kk = 0; kk < 4; kk++) {
            uint32_t v0 = __shfl_sync(0xffffffffu, pf[kk][0], srcA);
            uint32_t v1 = __shfl_sync(0xffffffffu, pf[kk][1], srcA);
            uint32_t w0 = __shfl_sync(0xffffffffu, pf[kk][0], srcB);
            uint32_t w1 = __shfl_sync(0xffffffffu, pf[kk][1], srcB);
            uint32_t v2 = __shfl_sync(0xffffffffu, pf[kk][2], srcA);
            uint32_t v3 = __shfl_sync(0xffffffffu, pf[kk][3], srcA);
            uint32_t w2 = __shfl_sync(0xffffffffu, pf[kk][2], srcB);
            uint32_t w3 = __shfl_sync(0xffffffffu, pf[kk][3], srcB);
            uint32_t af[4];
            af[0] = (qd & 1) ? v1 : v0;
            af[2] = (qd & 1) ? w1 : w0;
            af[1] = (qd & 1) ? v3 : v2;
            af[3] = (qd & 1) ? w3 : w2;
            #pragma unroll
            for (int j = 0; j < 8; j++) {
                uint32_t b0 = Vs[(8 * kk + qd) * LDV + 8 * j + g];
                uint32_t b1 = Vs[(8 * kk + qd + 4) * LDV + 8 * j + g];
                MMA_TF32(oa[j], af, b0, b1);
            }
        }

        if (it < NIT - 1) STORET(1 - s);
        __syncthreads();
    }

    // ---- epilogue ----
    l0 += __shfl_xor_sync(0xffffffffu, l0, 1);
    l0 += __shfl_xor_sync(0xffffffffu, l0, 2);
    l1 += __shfl_xor_sync(0xffffffffu, l1, 1);
    l1 += __shfl_xor_sync(0xffffffffu, l1, 2);
    float li0 = 1.0f / l0, li1 = 1.0f / l1;

    float* ob = vals + qrow0 * EMB + h * HD;
    #pragma unroll
    for (int j = 0; j < 8; j++) {
        float2 x0 = make_float2(oa[j][0] * li0, oa[j][1] * li0);
        float2 x1 = make_float2(oa[j][2] * li1, oa[j][3] * li1);
        *(float2*)&ob[(size_t)g * EMB + 8 * j + 2 * qd]       = x0;
        *(float2*)&ob[(size_t)(g + 8) * EMB + 8 * j + 2 * qd] = x1;
    }
}

// ======================= launch =============================================
extern "C" void kernel_launch(void* const* d_in, const int* in_sizes, int n_in,
                              void* d_out, int out_size)
{
    const float* q_in = (const float*)d_in[0];
    const float* c_in = (const float*)d_in[1];
    const float* Wkv  = (const float*)d_in[2];
    const float* bkv  = (const float*)d_in[3];
    const float* Wo   = (const float*)d_in[4];
    const float* bo   = (const float*)d_in[5];
    float* out = (float*)d_out;

    float *kv_ptr, *vals_ptr, *wkvt_ptr, *wot_ptr;
    cudaGetSymbolAddress((void**)&kv_ptr,  g_kv);
    cudaGetSymbolAddress((void**)&vals_ptr, g_vals);
    cudaGetSymbolAddress((void**)&wkvt_ptr, g_wkvt);
    cudaGetSymbolAddress((void**)&wot_ptr,  g_wot);

    const int M = BATCH * SEQ;             // 8192

    // 0) transpose weights
    transpose_kernel<<<dim3((2 * EMB) / 32, EMB / 32), dim3(32, 8)>>>(
        Wkv, wkvt_ptr, EMB, 2 * EMB);
    transpose_kernel<<<dim3(EMB / 32, EMB / 32), dim3(32, 8)>>>(
        Wo, wot_ptr, EMB, EMB);

    // 1) kv = c @ W_kv + b_kv         [8192, 2048]
    cudaFuncSetAttribute(gemm_mma_tf32,
                         cudaFuncAttributeMaxDynamicSharedMemorySize, GSMEM);
    gemm_mma_tf32<<<dim3((2 * EMB) / 128, M / 128), 256, GSMEM>>>(
        c_in, wkvt_ptr, bkv, kv_ptr, M, 2 * EMB, EMB);

    // 2) flash attention -> values    [8192, 1024]
    size_t smem = (size_t)2 * STG_SZ * sizeof(uint32_t);   // 35.8 KB
    cudaFuncSetAttribute(flash_attn_mma,
                         cudaFuncAttributeMaxDynamicSharedMemorySize, (int)smem);
    flash_attn_mma<<<dim3(SEQ / 128, BATCH * NH), 256, smem>>>(
        q_in, kv_ptr, vals_ptr);

    // 3) out = values @ W_o + b_o     [8192, 1024]
    gemm_mma_tf32<<<dim3(EMB / 128, M / 128), 256, GSMEM>>>(
        vals_ptr, wot_ptr, bo, out, M, EMB, EMB);
}